// round 8
// baseline (speedup 1.0000x reference)
#include <cuda_runtime.h>
#include <cuda_bf16.h>

#define NBINS 100
#define THREADS 256
#define BLOCKS 1184          // 8 blocks/SM on 148 SMs, single wave

__device__ int g_hist[NBINS];
__device__ unsigned int g_ticket;        // zero-init; restored every launch
__device__ int g_part[BLOCKS][128];      // per-block L2 rows, 512B stride; zero-init,
                                         // re-zeroed by owner block every launch

__global__ void __launch_bounds__(THREADS, 8) hist_kernel(
    const float4* __restrict__ x4, int n4,
    const float* __restrict__ tail, int ntail,
    const float* __restrict__ bounds,
    float* __restrict__ out)
{
    __shared__ float sb[NBINS + 1];
    __shared__ int   sh[NBINS * 32];     // sh[bin*32 + lane] -> bank == lane
    __shared__ int   is_last;

    const int tid  = threadIdx.x;
    const int lane = tid & 31;
    int* __restrict__ row = &g_part[blockIdx.x][0];

    if (tid <= NBINS) sb[tid] = bounds[tid];
    for (int i = tid; i < NBINS * 32; i += THREADS) sh[i] = 0;
    __syncthreads();

    // e = (x + 1e-6) * 100/1.000001 ; int part = bin. Exact except within
    // ~2.2e-5 (e-units) of a boundary; m = 2.5e-4 is a 10x safety margin.
    const float scale = 100.0f / 1.000001f;
    const float coff  = 1e-6f * (100.0f / 1.000001f);
    const float m     = 2.5e-4f;

    const int stride = gridDim.x * THREADS;
    int i = blockIdx.x * THREADS + tid;

    for (; i + stride < n4; i += 2 * stride) {
        float4 v0 = __ldcs(&x4[i]);
        float4 v1 = __ldcs(&x4[i + stride]);

        // v0 half -> shared-memory atomic unit (L1)
        {
            float xs[4] = {v0.x, v0.y, v0.z, v0.w};
            #pragma unroll
            for (int k = 0; k < 4; k++) {
                const float x = xs[k];
                const float e = fmaf(x, scale, coff);
                int b = min((int)e, NBINS - 1);
                const float d = e - rintf(e);
                if (fabsf(d) < m) {                  // rare exact path
                    if (x <= sb[b])          b -= 1;
                    else if (x > sb[b + 1])  b += 1;
                    b = max(0, min(b, NBINS - 1));
                }
                atomicAdd(&sh[(b << 5) | lane], 1);
            }
        }
        // v1 half -> L2 atomic unit (RED.ADD, no return, per-block row)
        {
            float xs[4] = {v1.x, v1.y, v1.z, v1.w};
            #pragma unroll
            for (int k = 0; k < 4; k++) {
                const float x = xs[k];
                const float e = fmaf(x, scale, coff);
                int b = min((int)e, NBINS - 1);
                const float d = e - rintf(e);
                if (fabsf(d) < m) {
                    if (x <= sb[b])          b -= 1;
                    else if (x > sb[b + 1])  b += 1;
                    b = max(0, min(b, NBINS - 1));
                }
                atomicAdd(&row[b], 1);               // REDG (result unused)
            }
        }
    }

    if (i < n4) {                            // one leftover float4 chunk
        float4 v0 = __ldcs(&x4[i]);
        float xs[4] = {v0.x, v0.y, v0.z, v0.w};
        #pragma unroll
        for (int k = 0; k < 4; k++) {
            const float x = xs[k];
            const float e = fmaf(x, scale, coff);
            int b = min((int)e, NBINS - 1);
            const float d = e - rintf(e);
            if (fabsf(d) < m) {
                if (x <= sb[b])          b -= 1;
                else if (x > sb[b + 1])  b += 1;
                b = max(0, min(b, NBINS - 1));
            }
            atomicAdd(&sh[(b << 5) | lane], 1);
        }
    }

    if (blockIdx.x == 0 && tid < ntail) {    // scalar tail
        const float x = tail[tid];
        const float e = fmaf(x, scale, coff);
        int b = min((int)e, NBINS - 1);
        const float d = e - rintf(e);
        if (fabsf(d) < m) {
            if (x <= sb[b])          b -= 1;
            else if (x > sb[b + 1])  b += 1;
            b = max(0, min(b, NBINS - 1));
        }
        atomicAdd(&sh[(b << 5) | lane], 1);
    }

    // make this block's REDs visible, then join
    __threadfence();
    __syncthreads();

    // reduce: smem lanes + own L2 row; re-zero row for next graph replay
    for (int b = tid; b < NBINS; b += THREADS) {
        int s = 0;
        #pragma unroll
        for (int j = 0; j < 32; j++)
            s += sh[(b << 5) | ((lane + j) & 31)];
        s += atomicAdd(&row[b], 0);          // coherent read of own row
        atomicExch(&row[b], 0);              // restore for next replay
        if (s) atomicAdd(&g_hist[b], s);
    }

    // last block writes the result and restores globals for the next replay
    __threadfence();
    if (tid == 0) {
        unsigned int old = atomicAdd(&g_ticket, 1u);
        is_last = (old == (unsigned int)(gridDim.x - 1));
    }
    __syncthreads();

    if (is_last) {
        for (int b = tid; b < NBINS; b += THREADS) {
            int v = atomicAdd(&g_hist[b], 0);
            out[b] = (float)v;
            atomicExch(&g_hist[b], 0);
        }
        if (tid == 0) atomicExch(&g_ticket, 0u);
    }
}

extern "C" void kernel_launch(void* const* d_in, const int* in_sizes, int n_in,
                              void* d_out, int out_size) {
    const float* x      = (const float*)d_in[0];
    const float* bounds = (const float*)d_in[1];
    const int n  = in_sizes[0];
    const int n4 = n >> 2;
    const int ntail = n & 3;

    hist_kernel<<<BLOCKS, THREADS>>>((const float4*)x, n4,
                                     x + (n4 << 2), ntail, bounds,
                                     (float*)d_out);
}

// round 9
// speedup vs baseline: 1.7883x; 1.7883x over previous
#include <cuda_runtime.h>
#include <cuda_bf16.h>

#define NBINS 100
#define BPAD  104            // padded bins per thread; (26*tid + bin/4)%32 ~conflict-free
#define THREADS 256
#define BLOCKS 1184          // 8 blocks/SM on 148 SMs, single wave

__device__ int g_hist[NBINS];
__device__ unsigned int g_ticket;   // zero-init; restored to 0 every launch

__global__ void __launch_bounds__(THREADS, 8) hist_kernel(
    const float4* __restrict__ x4, int n4,
    const float* __restrict__ tail, int ntail,
    const float* __restrict__ bounds,
    float* __restrict__ out)
{
    __shared__ float sb[NBINS + 1];
    // Per-THREAD exclusive u8 counters: cnt[tid*104 + bin]. No atomics, no
    // races. Max per-thread count ~88 << 255. 26.6KB -> still 8 blocks/SM.
    __shared__ unsigned char cnt[THREADS * BPAD];
    __shared__ int is_last;

    const int tid = threadIdx.x;

    if (tid <= NBINS) sb[tid] = bounds[tid];
    {
        unsigned int* z = (unsigned int*)cnt;
        #pragma unroll
        for (int i = tid; i < THREADS * BPAD / 4; i += THREADS) z[i] = 0u;
    }
    __syncthreads();

    unsigned char* __restrict__ my = &cnt[tid * BPAD];

    // e = (x + 1e-6) * 100/1.000001 ; int part = bin. Exact except within
    // ~2.2e-5 (e-units) of a boundary; m = 2.5e-4 is a 10x safety margin.
    const float scale = 100.0f / 1.000001f;
    const float coff  = 1e-6f * (100.0f / 1.000001f);
    const float m     = 2.5e-4f;

    const int stride = gridDim.x * THREADS;
    int i = blockIdx.x * THREADS + tid;

    for (; i + stride < n4; i += 2 * stride) {
        float4 v0 = __ldcs(&x4[i]);
        float4 v1 = __ldcs(&x4[i + stride]);

        float xs[8] = {v0.x, v0.y, v0.z, v0.w, v1.x, v1.y, v1.z, v1.w};
        #pragma unroll
        for (int k = 0; k < 8; k++) {
            const float x = xs[k];
            const float e = fmaf(x, scale, coff);
            int b = min((int)e, NBINS - 1);
            const float d = e - rintf(e);
            if (fabsf(d) < m) {                  // rare exact path (~0.05%)
                if (x <= sb[b])          b -= 1; // no-op if already correct
                else if (x > sb[b + 1])  b += 1;
                b = max(0, min(b, NBINS - 1));
            }
            my[b] += 1;                          // LDS.U8 + IADD + STS.U8
        }
    }

    if (i < n4) {                                // one leftover float4 chunk
        float4 v0 = __ldcs(&x4[i]);
        float xs[4] = {v0.x, v0.y, v0.z, v0.w};
        #pragma unroll
        for (int k = 0; k < 4; k++) {
            const float x = xs[k];
            const float e = fmaf(x, scale, coff);
            int b = min((int)e, NBINS - 1);
            const float d = e - rintf(e);
            if (fabsf(d) < m) {
                if (x <= sb[b])          b -= 1;
                else if (x > sb[b + 1])  b += 1;
                b = max(0, min(b, NBINS - 1));
            }
            my[b] += 1;
        }
    }

    if (blockIdx.x == 0 && tid < ntail) {        // scalar tail (own counters)
        const float x = tail[tid];
        const float e = fmaf(x, scale, coff);
        int b = min((int)e, NBINS - 1);
        const float d = e - rintf(e);
        if (fabsf(d) < m) {
            if (x <= sb[b])          b -= 1;
            else if (x > sb[b + 1])  b += 1;
            b = max(0, min(b, NBINS - 1));
        }
        my[b] += 1;
    }

    __syncthreads();

    // reduce: 200 threads; thread = (bin, half) sums 128 u8 column entries
    if (tid < 2 * NBINS) {
        const int b = tid % NBINS;
        const int h = tid / NBINS;               // 0 or 1
        int s = 0;
        const int t0 = h * (THREADS / 2);
        #pragma unroll 8
        for (int t = t0; t < t0 + THREADS / 2; t++)
            s += cnt[t * BPAD + b];
        if (s) atomicAdd(&g_hist[b], s);
    }

    // last block writes the result and restores globals for the next replay
    __threadfence();
    if (tid == 0) {
        unsigned int old = atomicAdd(&g_ticket, 1u);
        is_last = (old == (unsigned int)(gridDim.x - 1));
    }
    __syncthreads();

    if (is_last) {
        for (int b = tid; b < NBINS; b += THREADS) {
            int v = atomicAdd(&g_hist[b], 0);    // L2-coherent read
            out[b] = (float)v;
            atomicExch(&g_hist[b], 0);
        }
        if (tid == 0) atomicExch(&g_ticket, 0u);
    }
}

extern "C" void kernel_launch(void* const* d_in, const int* in_sizes, int n_in,
                              void* d_out, int out_size) {
    const float* x      = (const float*)d_in[0];
    const float* bounds = (const float*)d_in[1];
    const int n  = in_sizes[0];
    const int n4 = n >> 2;
    const int ntail = n & 3;

    hist_kernel<<<BLOCKS, THREADS>>>((const float4*)x, n4,
                                     x + (n4 << 2), ntail, bounds,
                                     (float*)d_out);
}

// round 11
// speedup vs baseline: 3.1271x; 1.7486x over previous
#include <cuda_runtime.h>
#include <cuda_bf16.h>

#define NBINS 100
#define THREADS 512
#define BLOCKS 592           // 4 blocks/SM on 148 SMs, single wave (2048 thr/SM)

__device__ int g_hist[NBINS];
__device__ unsigned int g_ticket;   // zero-init; restored to 0 every launch

__global__ void __launch_bounds__(THREADS, 4) hist_kernel(
    const float4* __restrict__ x4, int n4,
    const float* __restrict__ tail, int ntail,
    const float* __restrict__ bounds,
    float* __restrict__ out)
{
    __shared__ __align__(16) float sb[NBINS + 1];
    __shared__ __align__(16) int   sh[NBINS * 32];  // sh[bin*32+lane], bank==lane
    __shared__ int is_last;

    const int tid  = threadIdx.x;
    const int lane = tid & 31;

    if (tid <= NBINS) sb[tid] = bounds[tid];
    for (int i = tid; i < NBINS * 32; i += THREADS) sh[i] = 0;
    __syncthreads();

    // e = (x + 1e-6) * 100/1.000001 ; int part = bin. Exact except within
    // ~2.2e-5 (e-units) of a boundary; m = 2.5e-4 is a 10x safety margin.
    const float scale = 100.0f / 1.000001f;
    const float coff  = 1e-6f * (100.0f / 1.000001f);
    const float m     = 2.5e-4f;

    const int stride = gridDim.x * THREADS;
    int i = blockIdx.x * THREADS + tid;

    for (; i + stride < n4; i += 2 * stride) {
        float4 v0 = __ldcs(&x4[i]);
        float4 v1 = __ldcs(&x4[i + stride]);

        float xs[8] = {v0.x, v0.y, v0.z, v0.w, v1.x, v1.y, v1.z, v1.w};
        #pragma unroll
        for (int k = 0; k < 8; k++) {
            const float x = xs[k];
            const float e = fmaf(x, scale, coff);
            const int  b0 = (int)e;
            const float f = e - (float)b0;
            int b = min(b0, NBINS - 1);
            if (f < m || f > 1.0f - m) {         // rare exact path (~0.05%)
                if (x <= sb[b])          b -= 1;
                else if (x > sb[b + 1])  b += 1;
                b = max(0, min(b, NBINS - 1));
            }
            atomicAdd(&sh[(b << 5) | lane], 1);  // bank = lane
        }
    }

    if (i < n4) {                                // one leftover float4 chunk
        float4 v0 = __ldcs(&x4[i]);
        float xs[4] = {v0.x, v0.y, v0.z, v0.w};
        #pragma unroll
        for (int k = 0; k < 4; k++) {
            const float x = xs[k];
            const float e = fmaf(x, scale, coff);
            const int  b0 = (int)e;
            const float f = e - (float)b0;
            int b = min(b0, NBINS - 1);
            if (f < m || f > 1.0f - m) {
                if (x <= sb[b])          b -= 1;
                else if (x > sb[b + 1])  b += 1;
                b = max(0, min(b, NBINS - 1));
            }
            atomicAdd(&sh[(b << 5) | lane], 1);
        }
    }

    if (blockIdx.x == 0 && tid < ntail) {        // scalar tail
        const float x = tail[tid];
        const float e = fmaf(x, scale, coff);
        const int  b0 = (int)e;
        const float f = e - (float)b0;
        int b = min(b0, NBINS - 1);
        if (f < m || f > 1.0f - m) {
            if (x <= sb[b])          b -= 1;
            else if (x > sb[b + 1])  b += 1;
            b = max(0, min(b, NBINS - 1));
        }
        atomicAdd(&sh[(b << 5) | lane], 1);
    }

    __syncthreads();

    // reduce: thread b sums its bin's 32 lane-counters as 8 int4 reads
    // (sh is 16B-aligned; bin*128B + j*16B keeps threads on distinct banks)
    if (tid < NBINS) {
        const int4* __restrict__ p = (const int4*)&sh[tid << 5];
        int s = 0;
        #pragma unroll
        for (int j = 0; j < 8; j++) {
            int4 v = p[j];
            s += v.x + v.y + v.z + v.w;
        }
        if (s) atomicAdd(&g_hist[tid], s);
    }

    // last block writes the result and restores globals for the next replay
    __threadfence();
    if (tid == 0) {
        unsigned int old = atomicAdd(&g_ticket, 1u);
        is_last = (old == (unsigned int)(gridDim.x - 1));
    }
    __syncthreads();

    if (is_last) {
        if (tid < NBINS) {
            int v = atomicAdd(&g_hist[tid], 0);  // L2-coherent read
            out[tid] = (float)v;
            atomicExch(&g_hist[tid], 0);
        }
        if (tid == 0) atomicExch(&g_ticket, 0u);
    }
}

extern "C" void kernel_launch(void* const* d_in, const int* in_sizes, int n_in,
                              void* d_out, int out_size) {
    const float* x      = (const float*)d_in[0];
    const float* bounds = (const float*)d_in[1];
    const int n  = in_sizes[0];
    const int n4 = n >> 2;
    const int ntail = n & 3;

    hist_kernel<<<BLOCKS, THREADS>>>((const float4*)x, n4,
                                     x + (n4 << 2), ntail, bounds,
                                     (float*)d_out);
}